// round 5
// baseline (speedup 1.0000x reference)
#include <cuda_runtime.h>
#include <math.h>

// ---------------------------------------------------------------------------
// Problem constants
// ---------------------------------------------------------------------------
#define Bq    1024      // batch
#define NF    128       // n_feat
#define D     256       // d_main
#define DI    512       // d_int
#define NC    100000    // n candidates
#define CTX   96        // context size (top-k)
#define NCLS  10
#define CAPK  3584      // top-k candidate buffer capacity (smem)

// ---------------------------------------------------------------------------
// Device scratch (static __device__ arrays: the sanctioned alloc-free scratch)
// ---------------------------------------------------------------------------
__device__ float g_h1  [(size_t)NC * D];     // cand hidden            102 MB
__device__ float g_ki  [(size_t)NC * D];     // candidate keys         102 MB
__device__ float g_nn  [NC];                 // |ki|^2
__device__ float g_x   [Bq * D];             // x = lin(x_num)
__device__ float g_k   [Bq * D];             // k = K(x)
__device__ float g_kk  [Bq];                 // |k|^2
__device__ float g_d2  [(size_t)Bq * NC];    // distance matrix        410 MB
__device__ int   g_I   [Bq * CTX];           // top-k indices
__device__ int   g_cls [Bq * CTX];           // gathered labels
__device__ float g_S   [Bq * CTX];           // exact squared distances
__device__ float g_w   [Bq * CTX];           // softmax weights
__device__ float g_diff[(size_t)Bq * CTX * D];   // k - ki              100 MB
__device__ float g_mh  [(size_t)Bq * CTX * DI];  // relu(diff@T_W1+b)   201 MB
__device__ float g_V   [(size_t)Bq * CTX * D];   // mh @ T_W2           100 MB
__device__ float g_xr  [Bq * D];             // x + V (residual)
__device__ float g_ln  [Bq * D];             // LN buffer
__device__ float g_p1  [Bq * DI];            // predictor hidden
__device__ float g_x2  [Bq * D];             // pre-head

// ---------------------------------------------------------------------------
// Generic SGEMM (NN): C = act(A[M,K] @ B[K,N] + bias + addsrc)
// BM=BN=128, BK=8, 256 threads, 8x8 per-thread.
// Requirements: K % 8 == 0, N % 128 == 0 (true for all NN uses: N=256/512).
// M is guarded.
// ---------------------------------------------------------------------------
__global__ void __launch_bounds__(256) sgemm_nn(
    int M, int N, int K,
    const float* __restrict__ A, const float* __restrict__ Bm,
    const float* __restrict__ bias, const float* __restrict__ addsrc,
    float* __restrict__ C, int relu)
{
    __shared__ float As[8][132];   // padded rows: conflict-free transposed store
    __shared__ float Bs[8][132];
    const int t  = threadIdx.x;
    const int m0 = blockIdx.y * 128;
    const int n0 = blockIdx.x * 128;
    const int tx = t & 15, ty = t >> 4;
    const int arow = t >> 1, acol = (t & 1) * 4;
    const int brow = t >> 5, bcol = (t & 31) * 4;

    float acc[8][8];
#pragma unroll
    for (int i = 0; i < 8; i++)
#pragma unroll
        for (int j = 0; j < 8; j++) acc[i][j] = 0.f;

    const int gm_a = m0 + arow;
    for (int k0 = 0; k0 < K; k0 += 8) {
        float4 av = make_float4(0.f, 0.f, 0.f, 0.f);
        if (gm_a < M)
            av = *reinterpret_cast<const float4*>(A + (size_t)gm_a * K + k0 + acol);
        As[acol + 0][arow] = av.x; As[acol + 1][arow] = av.y;
        As[acol + 2][arow] = av.z; As[acol + 3][arow] = av.w;

        float4 bv = *reinterpret_cast<const float4*>(Bm + (size_t)(k0 + brow) * N + n0 + bcol);
        Bs[brow][bcol + 0] = bv.x; Bs[brow][bcol + 1] = bv.y;
        Bs[brow][bcol + 2] = bv.z; Bs[brow][bcol + 3] = bv.w;
        __syncthreads();

#pragma unroll
        for (int kk = 0; kk < 8; kk++) {
            float a[8], b[8];
#pragma unroll
            for (int i = 0; i < 8; i++) a[i] = As[kk][ty * 8 + i];
#pragma unroll
            for (int j = 0; j < 8; j++) b[j] = Bs[kk][tx * 8 + j];
#pragma unroll
            for (int i = 0; i < 8; i++)
#pragma unroll
                for (int j = 0; j < 8; j++)
                    acc[i][j] = fmaf(a[i], b[j], acc[i][j]);
        }
        __syncthreads();
    }

#pragma unroll
    for (int i = 0; i < 8; i++) {
        int gm = m0 + ty * 8 + i;
        if (gm >= M) continue;
#pragma unroll
        for (int j = 0; j < 8; j++) {
            int gn = n0 + tx * 8 + j;
            float v = acc[i][j];
            if (bias)   v += bias[gn];
            if (addsrc) v += addsrc[(size_t)gm * N + gn];
            if (relu)   v = fmaxf(v, 0.f);
            C[(size_t)gm * N + gn] = v;
        }
    }
}

// ---------------------------------------------------------------------------
// Distance GEMM (NT): C[m,n] = |a_m|^2 + |b_n|^2 - 2 * dot(A[m,:], Bt[n,:])
// A: [M,K] row-major, Bt: [N,K] row-major. K % 8 == 0. M,N guarded.
// ---------------------------------------------------------------------------
__global__ void __launch_bounds__(256) dist_nt(
    int M, int N, int K,
    const float* __restrict__ A, const float* __restrict__ Bt,
    const float* __restrict__ an2, const float* __restrict__ bn2,
    float* __restrict__ C)
{
    __shared__ float As[8][132];
    __shared__ float Bs[8][132];
    const int t  = threadIdx.x;
    const int m0 = blockIdx.y * 128;
    const int n0 = blockIdx.x * 128;
    const int tx = t & 15, ty = t >> 4;
    const int arow = t >> 1, acol = (t & 1) * 4;   // A tile
    const int brow = t >> 1, bcol = (t & 1) * 4;   // B tile (rows are n)

    float acc[8][8];
#pragma unroll
    for (int i = 0; i < 8; i++)
#pragma unroll
        for (int j = 0; j < 8; j++) acc[i][j] = 0.f;

    const int gm_a = m0 + arow;
    const int gn_b = n0 + brow;
    for (int k0 = 0; k0 < K; k0 += 8) {
        float4 av = make_float4(0.f, 0.f, 0.f, 0.f);
        if (gm_a < M)
            av = *reinterpret_cast<const float4*>(A + (size_t)gm_a * K + k0 + acol);
        As[acol + 0][arow] = av.x; As[acol + 1][arow] = av.y;
        As[acol + 2][arow] = av.z; As[acol + 3][arow] = av.w;

        float4 bv = make_float4(0.f, 0.f, 0.f, 0.f);
        if (gn_b < N)
            bv = *reinterpret_cast<const float4*>(Bt + (size_t)gn_b * K + k0 + bcol);
        Bs[bcol + 0][brow] = bv.x; Bs[bcol + 1][brow] = bv.y;
        Bs[bcol + 2][brow] = bv.z; Bs[bcol + 3][brow] = bv.w;
        __syncthreads();

#pragma unroll
        for (int kk = 0; kk < 8; kk++) {
            float a[8], b[8];
#pragma unroll
            for (int i = 0; i < 8; i++) a[i] = As[kk][ty * 8 + i];
#pragma unroll
            for (int j = 0; j < 8; j++) b[j] = Bs[kk][tx * 8 + j];
#pragma unroll
            for (int i = 0; i < 8; i++)
#pragma unroll
                for (int j = 0; j < 8; j++)
                    acc[i][j] = fmaf(a[i], b[j], acc[i][j]);
        }
        __syncthreads();
    }

#pragma unroll
    for (int i = 0; i < 8; i++) {
        int gm = m0 + ty * 8 + i;
        if (gm >= M) continue;
        float a2 = an2[gm];
#pragma unroll
        for (int j = 0; j < 8; j++) {
            int gn = n0 + tx * 8 + j;
            if (gn >= N) continue;
            C[(size_t)gm * N + gn] = a2 + bn2[gn] - 2.f * acc[i][j];
        }
    }
}

// ---------------------------------------------------------------------------
// Row squared norms: out[r] = sum_j X[r,j]^2   (row length == D == blockDim)
// ---------------------------------------------------------------------------
__global__ void rownorm2(const float* __restrict__ X, float* __restrict__ out)
{
    int r = blockIdx.x, t = threadIdx.x;
    float v = X[(size_t)r * D + t];
    __shared__ float red[256];
    red[t] = v * v;
    __syncthreads();
    for (int k = 128; k > 0; k >>= 1) {
        if (t < k) red[t] += red[t + k];
        __syncthreads();
    }
    if (t == 0) out[r] = red[0];
}

// ---------------------------------------------------------------------------
// Top-96 smallest per row via histogram radix-select.
// 1 CTA / row, 256 threads. Monotone float->uint key; 12-bit level-1
// histogram; optional 8-bit level-2 refinement; survivors collected to smem
// and extracted by repeated argmin. Output order is arbitrary (downstream is
// permutation-invariant: gather + softmax + weighted sum).
// ---------------------------------------------------------------------------
__device__ __forceinline__ unsigned f2u(float f) {
    unsigned u = __float_as_uint(f);
    return (u & 0x80000000u) ? ~u : (u | 0x80000000u);
}

__global__ void __launch_bounds__(256) topk_kernel(
    const float* __restrict__ D2, int N, int* __restrict__ I)
{
    const int row = blockIdx.x;
    const float* __restrict__ drow = D2 + (size_t)row * N;
    const int t = threadIdx.x;

    __shared__ unsigned hist[4096];
    __shared__ unsigned bufKey[CAPK];
    __shared__ int      bufIdx[CAPK];
    __shared__ unsigned pref[256];
    __shared__ unsigned long long red[256];
    __shared__ int sh_b1, sh_b2, sh_before, sh_nOut, sh_nBuf;

    // ---- pass 1: 12-bit histogram (key >> 20) ----
    for (int i = t; i < 4096; i += 256) hist[i] = 0;
    __syncthreads();
    for (int i = t; i < N; i += 256)
        atomicAdd(&hist[f2u(drow[i]) >> 20], 1u);
    __syncthreads();

    // ---- find bucket containing rank 95 (0-based) ----
    unsigned ls = 0;
#pragma unroll
    for (int j = 0; j < 16; j++) ls += hist[t * 16 + j];
    pref[t] = ls;
    __syncthreads();
    if (t == 0) {
        unsigned run = 0;
        for (int i = 0; i < 256; i++) { unsigned s = pref[i]; pref[i] = run; run += s; }
    }
    __syncthreads();
    {
        unsigned run = pref[t];
#pragma unroll
        for (int j = 0; j < 16; j++) {
            unsigned c = hist[t * 16 + j];
            if (run <= 95u && 95u < run + c) { sh_b1 = t * 16 + j; sh_before = (int)run; }
            run += c;
        }
    }
    __syncthreads();
    const int b1 = sh_b1;
    int before = sh_before;
    const unsigned cnt_b1 = hist[b1];
    __syncthreads();

    // ---- optional level-2 refinement (bits 19..12) ----
    const int use2 = (cnt_b1 > CAPK);
    int b2 = -1;
    if (use2) {
        hist[t] = 0;                 // reuse first 256 buckets
        __syncthreads();
        for (int i = t; i < N; i += 256) {
            unsigned k = f2u(drow[i]);
            if ((int)(k >> 20) == b1) atomicAdd(&hist[(k >> 12) & 255u], 1u);
        }
        __syncthreads();
        if (t == 0) {
            unsigned run = 0;
            unsigned tgt = (unsigned)(95 - before);
            for (int i = 0; i < 256; i++) {
                unsigned c = hist[i];
                if (run <= tgt && tgt < run + c) { sh_b2 = i; sh_before = before + (int)run; break; }
                run += c;
            }
        }
        __syncthreads();
        b2 = sh_b2;
        before = sh_before;
    }

    // ---- collect: strict-less -> direct emit; equal-bucket -> buffer ----
    if (t == 0) { sh_nOut = 0; sh_nBuf = 0; }
    __syncthreads();
    for (int i = t; i < N; i += 256) {
        unsigned k = f2u(drow[i]);
        unsigned hb = k >> 20;
        bool less, eq;
        if (!use2) {
            less = hb < (unsigned)b1; eq = (hb == (unsigned)b1);
        } else {
            unsigned sb = (k >> 12) & 255u;
            less = (hb < (unsigned)b1) || (hb == (unsigned)b1 && sb < (unsigned)b2);
            eq   = (hb == (unsigned)b1 && sb == (unsigned)b2);
        }
        if (less) {
            int p = atomicAdd(&sh_nOut, 1);
            if (p < CTX) I[row * CTX + p] = i;
        } else if (eq) {
            int p = atomicAdd(&sh_nBuf, 1);
            if (p < CAPK) { bufKey[p] = k; bufIdx[p] = i; }
        }
    }
    __syncthreads();

    const int nOut = min(sh_nOut, CTX);     // == before (strict-less count)
    const int bc   = min(sh_nBuf, CAPK);
    const int need = CTX - nOut;

    // ---- repeated argmin over survivor buffer ----
    for (int it = 0; it < need; it++) {
        unsigned long long best = ~0ull;
        for (int i = t; i < bc; i += 256) {
            unsigned long long v = ((unsigned long long)bufKey[i] << 32) | (unsigned)i;
            if (v < best) best = v;
        }
        red[t] = best;
        __syncthreads();
        for (int s = 128; s > 0; s >>= 1) {
            if (t < s && red[t + s] < red[t]) red[t] = red[t + s];
            __syncthreads();
        }
        if (t == 0) {
            int p = (int)(red[0] & 0xffffffffu);
            I[row * CTX + nOut + it] = bufIdx[p];
            bufKey[p] = 0xFFFFFFFFu;
        }
        __syncthreads();
    }
}

// ---------------------------------------------------------------------------
// Gather ki, compute diff = k - ki, exact S = |diff|^2, labels.
// 1 CTA per (b, c) pair, 256 threads (= D).
// ---------------------------------------------------------------------------
__global__ void gather_diff(
    const float* __restrict__ kq, const float* __restrict__ ki,
    const int* __restrict__ I, const int* __restrict__ cy,
    float* __restrict__ diff, float* __restrict__ S, int* __restrict__ cls)
{
    const int bc = blockIdx.x;
    const int t  = threadIdx.x;
    const int b  = bc / CTX;
    const int idx = I[bc];
    float d = kq[(size_t)b * D + t] - ki[(size_t)idx * D + t];
    diff[(size_t)bc * D + t] = d;
    __shared__ float red[256];
    red[t] = d * d;
    __syncthreads();
    for (int k = 128; k > 0; k >>= 1) {
        if (t < k) red[t] += red[t + k];
        __syncthreads();
    }
    if (t == 0) { S[bc] = red[0]; cls[bc] = cy[idx]; }
}

// ---------------------------------------------------------------------------
// Softmax over CTX=96 values per row. 128 threads.
// ---------------------------------------------------------------------------
__global__ void softmax96(const float* __restrict__ S, float* __restrict__ w)
{
    const int b = blockIdx.x, t = threadIdx.x;
    __shared__ float red[128];
    float v = (t < CTX) ? S[b * CTX + t] : -INFINITY;
    red[t] = v;
    __syncthreads();
    for (int k = 64; k > 0; k >>= 1) {
        if (t < k) red[t] = fmaxf(red[t], red[t + k]);
        __syncthreads();
    }
    float mx = red[0];
    __syncthreads();
    float e = (t < CTX) ? expf(v - mx) : 0.f;
    red[t] = e;
    __syncthreads();
    for (int k = 64; k > 0; k >>= 1) {
        if (t < k) red[t] += red[t + k];
        __syncthreads();
    }
    float sm = red[0];
    if (t < CTX) w[b * CTX + t] = e / sm;
}

// ---------------------------------------------------------------------------
// xr[b,:] = x[b,:] + sum_c w[b,c] * (V[b,c,:] + Y_emb[cls[b,c],:])
// ---------------------------------------------------------------------------
__global__ void aggregate(
    const float* __restrict__ x, const float* __restrict__ w,
    const float* __restrict__ V, const int* __restrict__ cls,
    const float* __restrict__ Yemb, float* __restrict__ xo)
{
    const int b = blockIdx.x, t = threadIdx.x;
    float acc = x[b * D + t];
    const int base = b * CTX;
    for (int c = 0; c < CTX; c++) {
        float wv = w[base + c];
        int   cl = cls[base + c];
        acc += wv * (V[(size_t)(base + c) * D + t] + Yemb[cl * D + t]);
    }
    xo[b * D + t] = acc;
}

// ---------------------------------------------------------------------------
// LayerNorm over D=256 per row (ddof=0 variance, eps=1e-5). 256 threads.
// ---------------------------------------------------------------------------
__global__ void ln_kernel(
    const float* __restrict__ X, const float* __restrict__ sc,
    const float* __restrict__ bi, float* __restrict__ Y)
{
    const int b = blockIdx.x, t = threadIdx.x;
    float v = X[b * D + t];
    __shared__ float red[256];
    red[t] = v;
    __syncthreads();
    for (int k = 128; k > 0; k >>= 1) { if (t < k) red[t] += red[t + k]; __syncthreads(); }
    float m = red[0] * (1.f / D);
    __syncthreads();
    float dv = v - m;
    red[t] = dv * dv;
    __syncthreads();
    for (int k = 128; k > 0; k >>= 1) { if (t < k) red[t] += red[t + k]; __syncthreads(); }
    float var = red[0] * (1.f / D);
    Y[b * D + t] = dv * rsqrtf(var + 1e-5f) * sc[t] + bi[t];
}

// ---------------------------------------------------------------------------
// Head: out = relu(LN(x)) @ P_W + P_b   (10 outputs per row)
// ---------------------------------------------------------------------------
__global__ void head_kernel(
    const float* __restrict__ X, const float* __restrict__ sc,
    const float* __restrict__ bi, const float* __restrict__ PW,
    const float* __restrict__ Pb, float* __restrict__ out)
{
    const int b = blockIdx.x, t = threadIdx.x;
    float v = X[b * D + t];
    __shared__ float red[256];
    red[t] = v;
    __syncthreads();
    for (int k = 128; k > 0; k >>= 1) { if (t < k) red[t] += red[t + k]; __syncthreads(); }
    float m = red[0] * (1.f / D);
    __syncthreads();
    float dv = v - m;
    red[t] = dv * dv;
    __syncthreads();
    for (int k = 128; k > 0; k >>= 1) { if (t < k) red[t] += red[t + k]; __syncthreads(); }
    float var = red[0] * (1.f / D);
    __syncthreads();
    float h = fmaxf(dv * rsqrtf(var + 1e-5f) * sc[t] + bi[t], 0.f);
    for (int j = 0; j < NCLS; j++) {
        red[t] = h * PW[t * NCLS + j];
        __syncthreads();
        for (int k = 128; k > 0; k >>= 1) { if (t < k) red[t] += red[t + k]; __syncthreads(); }
        if (t == 0) out[b * NCLS + j] = red[0] + Pb[j];
        __syncthreads();
    }
}

// ---------------------------------------------------------------------------
// Launch
// ---------------------------------------------------------------------------
extern "C" void kernel_launch(void* const* d_in, const int* in_sizes, int n_in,
                              void* d_out, int out_size)
{
    (void)n_in; (void)out_size;
    const float* x_num    = (const float*)d_in[0];
    const float* cand_num = (const float*)d_in[1];
    const int*   cand_y   = (const int*)d_in[2];
    // d_in[3] may be the scalar context_size; detect and skip it.
    const int base = (in_sizes[3] == 1) ? 4 : 3;
    const float* W_lin   = (const float*)d_in[base + 0];
    const float* b_lin   = (const float*)d_in[base + 1];
    const float* W_K     = (const float*)d_in[base + 2];
    const float* b_K     = (const float*)d_in[base + 3];
    const float* Y_emb   = (const float*)d_in[base + 4];
    const float* T_W1    = (const float*)d_in[base + 5];
    const float* T_b1    = (const float*)d_in[base + 6];
    const float* T_W2    = (const float*)d_in[base + 7];
    const float* bp_ln_s = (const float*)d_in[base + 8];
    const float* bp_ln_b = (const float*)d_in[base + 9];
    const float* bp_W1   = (const float*)d_in[base + 10];
    const float* bp_b1   = (const float*)d_in[base + 11];
    const float* bp_W2   = (const float*)d_in[base + 12];
    const float* bp_b2   = (const float*)d_in[base + 13];
    const float* P_ln_s  = (const float*)d_in[base + 14];
    const float* P_ln_b  = (const float*)d_in[base + 15];
    const float* P_W     = (const float*)d_in[base + 16];
    const float* P_b     = (const float*)d_in[base + 17];
    float* out = (float*)d_out;

    float *h1, *ki, *nn2, *xb, *kb, *kk2, *d2, *diff, *mh, *Vb, *xr, *lnb, *p1, *x2;
    float *Sb, *wb;
    int *Ib, *clsb;
    cudaGetSymbolAddress((void**)&h1,  g_h1);
    cudaGetSymbolAddress((void**)&ki,  g_ki);
    cudaGetSymbolAddress((void**)&nn2, g_nn);
    cudaGetSymbolAddress((void**)&xb,  g_x);
    cudaGetSymbolAddress((void**)&kb,  g_k);
    cudaGetSymbolAddress((void**)&kk2, g_kk);
    cudaGetSymbolAddress((void**)&d2,  g_d2);
    cudaGetSymbolAddress((void**)&Ib,  g_I);
    cudaGetSymbolAddress((void**)&clsb,g_cls);
    cudaGetSymbolAddress((void**)&Sb,  g_S);
    cudaGetSymbolAddress((void**)&wb,  g_w);
    cudaGetSymbolAddress((void**)&diff,g_diff);
    cudaGetSymbolAddress((void**)&mh,  g_mh);
    cudaGetSymbolAddress((void**)&Vb,  g_V);
    cudaGetSymbolAddress((void**)&xr,  g_xr);
    cudaGetSymbolAddress((void**)&lnb, g_ln);
    cudaGetSymbolAddress((void**)&p1,  g_p1);
    cudaGetSymbolAddress((void**)&x2,  g_x2);

    const dim3 blk(256);

    // 1-2. candidate projections: ki_all = (cand @ W_lin + b) @ W_K + b_K
    sgemm_nn<<<dim3(D / 128, (NC + 127) / 128), blk>>>(NC, D, NF, cand_num, W_lin, b_lin, nullptr, h1, 0);
    sgemm_nn<<<dim3(D / 128, (NC + 127) / 128), blk>>>(NC, D, D,  h1,       W_K,   b_K,   nullptr, ki, 0);
    rownorm2<<<NC, 256>>>(ki, nn2);

    // 3-4. query projections
    sgemm_nn<<<dim3(D / 128, Bq / 128), blk>>>(Bq, D, NF, x_num, W_lin, b_lin, nullptr, xb, 0);
    sgemm_nn<<<dim3(D / 128, Bq / 128), blk>>>(Bq, D, D,  xb,    W_K,   b_K,   nullptr, kb, 0);
    rownorm2<<<Bq, 256>>>(kb, kk2);

    // 5. distance matrix + 6. exact top-96 per row
    dist_nt<<<dim3((NC + 127) / 128, Bq / 128), blk>>>(Bq, NC, D, kb, ki, kk2, nn2, d2);
    topk_kernel<<<Bq, 256>>>(d2, NC, Ib);

    // 7. gather, diff, exact S, labels; 8. softmax weights
    gather_diff<<<Bq * CTX, 256>>>(kb, ki, Ib, cand_y, diff, Sb, clsb);
    softmax96<<<Bq, 128>>>(Sb, wb);

    // 9-10. T MLP over [B*CTX, D]
    sgemm_nn<<<dim3(DI / 128, (Bq * CTX) / 128), blk>>>(Bq * CTX, DI, D,  diff, T_W1, T_b1, nullptr, mh, 1);
    sgemm_nn<<<dim3(D / 128,  (Bq * CTX) / 128), blk>>>(Bq * CTX, D,  DI, mh,   T_W2, nullptr, nullptr, Vb, 0);

    // 11. weighted aggregation + residual
    aggregate<<<Bq, 256>>>(xb, wb, Vb, clsb, Y_emb, xr);

    // 12-14. predictor block (LN -> Linear -> ReLU -> Linear, residual)
    ln_kernel<<<Bq, 256>>>(xr, bp_ln_s, bp_ln_b, lnb);
    sgemm_nn<<<dim3(DI / 128, Bq / 128), blk>>>(Bq, DI, D,  lnb, bp_W1, bp_b1, nullptr, p1, 1);
    sgemm_nn<<<dim3(D / 128,  Bq / 128), blk>>>(Bq, D,  DI, p1,  bp_W2, bp_b2, xr,      x2, 0);

    // 15. head
    head_kernel<<<Bq, 256>>>(x2, P_ln_s, P_ln_b, P_W, P_b, out);
}